// round 7
// baseline (speedup 1.0000x reference)
#include <cuda_runtime.h>

#define NODES 7
#define CH 256
#define PAIRS 128               // CH/2 channel pairs
#define HID 128
#define P_TOTAL 65536           // 16*64*64
#define PF 8                    // prefetch depth (channel pairs)

typedef unsigned long long ull;

// ---------------------------------------------------------------------------
// Packed f32x2 helpers
// ---------------------------------------------------------------------------
__device__ __forceinline__ ull fma2(ull a, ull b, ull c) {
    ull d;
    asm("fma.rn.f32x2 %0, %1, %2, %3;" : "=l"(d) : "l"(a), "l"(b), "l"(c));
    return d;
}
__device__ __forceinline__ ull pack2(float x, float y) {
    ull r;
    asm("mov.b64 %0, {%1, %2};" : "=l"(r) : "f"(x), "f"(y));
    return r;
}
__device__ __forceinline__ void unpack2(ull v, float& x, float& y) {
    asm("mov.b64 {%0, %1}, %2;" : "=f"(x), "=f"(y) : "l"(v));
}
__device__ __forceinline__ float ldcs32(const float* p) {
    float v;
    asm volatile("ld.global.cs.b32 %0, [%1];" : "=f"(v) : "l"(p));
    return v;
}
__device__ __forceinline__ void stcs32(float* p, float v) {
    asm volatile("st.global.cs.b32 [%0], %1;" :: "l"(p), "f"(v));
}

// ---------------------------------------------------------------------------
// Single fused kernel (R3 main body + in-block precompute prologue).
//   One spatial point per thread; f32x2 lanes carry a channel PAIR (2k,2k+1).
//   Grid: 512 blocks x 256 threads (b = blk>>8, 256 points per block).
// Prologue (per block): nw[n][c] = sum_h inp[b,n,h]*weight[h,c]  (c = tid),
//                       n2[n]    = sum_h inp[b,n,h]*nfh[h]        (tid < 7).
// weight (128KB) is read per block but L2-resident -> +128KB DRAM only.
// ---------------------------------------------------------------------------
__global__ void __launch_bounds__(256, 4) fused_kernel(
    const float* __restrict__ inp,     // [1,2,7,128]
    const float* __restrict__ res,     // [2, 256, 65536]
    const float* __restrict__ Wres,    // [256, 7]
    const float* __restrict__ nfh,     // [128,1]
    const float* __restrict__ weight,  // [128, 256]
    float* __restrict__ out)           // [2, 256, 65536]
{
    __shared__ float sh_in[NODES * HID];   // inp[b]  (3.5 KB)
    __shared__ float nw_s[NODES][CH];      // new_weight slice (7 KB)
    __shared__ float n2_s[NODES];
    __shared__ ull W2[PAIRS][8];           // (w[2k][n], w[2k+1][n])
    __shared__ ull NW2[PAIRS][8];          // (nw[n][2k], nw[n][2k+1])

    const int tid  = threadIdx.x;
    const int b    = blockIdx.x >> 8;   // 0..1
    const int tile = blockIdx.x & 255;  // 0..255

    // ---- Prologue stage 1: bring inp[b] into shared
    for (int i = tid; i < NODES * HID; i += 256)
        sh_in[i] = inp[b * NODES * HID + i];
    __syncthreads();

    // ---- Prologue stage 2: per-channel new_weight dot (c = tid)
    {
        float acc[NODES];
#pragma unroll
        for (int n = 0; n < NODES; ++n) acc[n] = 0.f;
#pragma unroll 8
        for (int h = 0; h < HID; ++h) {
            float wv = weight[h * CH + tid];      // coalesced; L2-hit
#pragma unroll
            for (int n = 0; n < NODES; ++n)
                acc[n] += sh_in[n * HID + h] * wv;
        }
#pragma unroll
        for (int n = 0; n < NODES; ++n)
            nw_s[n][tid] = acc[n];
    }
    // n2 (7 threads, serial 128-dot from shared)
    if (tid < NODES) {
        float s = 0.f;
#pragma unroll 8
        for (int h = 0; h < HID; ++h)
            s += sh_in[tid * HID + h] * nfh[h];
        n2_s[tid] = s;
    }
    // W2 packing from Wres (channel pairs, duplicated lanes)
    if (tid < PAIRS) {
        const int k = tid;
#pragma unroll
        for (int n = 0; n < NODES; ++n) {
            float w0 = Wres[(2 * k) * NODES + n];
            float w1 = Wres[(2 * k + 1) * NODES + n];
            W2[k][n] = pack2(w0, w1);
        }
        W2[k][7] = 0ull;
    }
    __syncthreads();

    // ---- Prologue stage 3: pack NW2 channel pairs
    if (tid < PAIRS) {
        const int k = tid;
#pragma unroll
        for (int n = 0; n < NODES; ++n)
            NW2[k][n] = pack2(nw_s[n][2 * k], nw_s[n][2 * k + 1]);
        NW2[k][7] = 0ull;
    }
    float n2s[NODES];
#pragma unroll
    for (int n = 0; n < NODES; ++n) n2s[n] = n2_s[n];
    __syncthreads();

    // =========================== main body (R3) ===========================
    const int p = tile * 256 + tid;                      // spatial point
    const float* rfp = res + (size_t)b * CH * P_TOTAL + p;

    ull acc[NODES];
#pragma unroll
    for (int n = 0; n < NODES; ++n) acc[n] = 0ull;

    // ---- Pass 1: n1[p,n] = sum_c rf[c,p]*W[c,n]; lo/hi = even/odd channels
    float a0[PF], a1[PF];
#pragma unroll
    for (int i = 0; i < PF; ++i) {
        a0[i] = ldcs32(rfp + (size_t)(2 * i) * P_TOTAL);
        a1[i] = ldcs32(rfp + (size_t)(2 * i + 1) * P_TOTAL);
    }

#pragma unroll 1
    for (int kb = 0; kb < PAIRS; kb += PF) {
#pragma unroll
        for (int i = 0; i < PF; ++i) {
            ull v = pack2(a0[i], a1[i]);
            if (kb + PF < PAIRS) {
                a0[i] = ldcs32(rfp + (size_t)(2 * (kb + PF + i)) * P_TOTAL);
                a1[i] = ldcs32(rfp + (size_t)(2 * (kb + PF + i) + 1) * P_TOTAL);
            }
            const ulonglong2* wr = (const ulonglong2*)(&W2[kb + i][0]);
            ulonglong2 w01 = wr[0];
            ulonglong2 w23 = wr[1];
            ulonglong2 w45 = wr[2];
            ulonglong2 w6p = wr[3];
            acc[0] = fma2(v, w01.x, acc[0]);
            acc[1] = fma2(v, w01.y, acc[1]);
            acc[2] = fma2(v, w23.x, acc[2]);
            acc[3] = fma2(v, w23.y, acc[3]);
            acc[4] = fma2(v, w45.x, acc[4]);
            acc[5] = fma2(v, w45.y, acc[5]);
            acc[6] = fma2(v, w6p.x, acc[6]);
        }
    }

    // ---- Softmax over 7 nodes (scalar, one point)
    float s[NODES];
#pragma unroll
    for (int n = 0; n < NODES; ++n) {
        float lo, hi;
        unpack2(acc[n], lo, hi);
        s[n] = lo + hi + n2s[n];
    }
    float m = s[0];
#pragma unroll
    for (int n = 1; n < NODES; ++n) m = fmaxf(m, s[n]);
    float e[NODES], sum = 0.f;
#pragma unroll
    for (int n = 0; n < NODES; ++n) { e[n] = __expf(s[n] - m); sum += e[n]; }
    float inv = __fdividef(1.f, sum);
    ull attn2[NODES];
#pragma unroll
    for (int n = 0; n < NODES; ++n) {
        float a = e[n] * inv;
        attn2[n] = pack2(a, a);
    }

    // ---- Pass 2: out[c,p] = relu(sum_n attn[n]*nw[n,c]), 2 channels per fma2
    float* op = out + (size_t)b * CH * P_TOTAL + p;
#pragma unroll 4
    for (int k = 0; k < PAIRS; ++k) {
        const ulonglong2* nr = (const ulonglong2*)(&NW2[k][0]);
        ulonglong2 q01 = nr[0];
        ulonglong2 q23 = nr[1];
        ulonglong2 q45 = nr[2];
        ulonglong2 q6p = nr[3];
        ull o = 0ull;
        o = fma2(attn2[0], q01.x, o);
        o = fma2(attn2[1], q01.y, o);
        o = fma2(attn2[2], q23.x, o);
        o = fma2(attn2[3], q23.y, o);
        o = fma2(attn2[4], q45.x, o);
        o = fma2(attn2[5], q45.y, o);
        o = fma2(attn2[6], q6p.x, o);
        float v0, v1;
        unpack2(o, v0, v1);
        stcs32(op + (size_t)(2 * k) * P_TOTAL,     fmaxf(v0, 0.f));
        stcs32(op + (size_t)(2 * k + 1) * P_TOTAL, fmaxf(v1, 0.f));
    }
}

// ---------------------------------------------------------------------------
extern "C" void kernel_launch(void* const* d_in, const int* in_sizes, int n_in,
                              void* d_out, int out_size) {
    const float* inp    = (const float*)d_in[0];  // [1,2,7,128]
    const float* res    = (const float*)d_in[1];  // [2,256,16,64,64]
    const float* Wres   = (const float*)d_in[2];  // [256,7]
    const float* nfh    = (const float*)d_in[3];  // [128,1]
    const float* weight = (const float*)d_in[4];  // [128,256]

    fused_kernel<<<512, 256>>>(inp, res, Wres, nfh, weight, (float*)d_out);
}

// round 8
// speedup vs baseline: 1.2212x; 1.2212x over previous
#include <cuda_runtime.h>

#define NODES 7
#define CH 256
#define PAIRS 128               // CH/2 channel pairs
#define HID 128
#define P_TOTAL 65536           // 16*64*64
#define PF 8                    // prefetch depth (channel pairs)

typedef unsigned long long ull;

__device__ float g_nw[2 * NODES * CH];          // new_weight [b, n, c]
__device__ float g_attn[2 * NODES * P_TOTAL];   // attn scratch [b, n, p] (3.7MB)

// ---------------------------------------------------------------------------
// Packed f32x2 helpers
// ---------------------------------------------------------------------------
__device__ __forceinline__ ull fma2(ull a, ull b, ull c) {
    ull d;
    asm("fma.rn.f32x2 %0, %1, %2, %3;" : "=l"(d) : "l"(a), "l"(b), "l"(c));
    return d;
}
__device__ __forceinline__ ull pack2(float x, float y) {
    ull r;
    asm("mov.b64 %0, {%1, %2};" : "=l"(r) : "f"(x), "f"(y));
    return r;
}
__device__ __forceinline__ void unpack2(ull v, float& x, float& y) {
    asm("mov.b64 {%0, %1}, %2;" : "=f"(x), "=f"(y) : "l"(v));
}
__device__ __forceinline__ float ldcs32(const float* p) {
    float v;
    asm volatile("ld.global.cs.b32 %0, [%1];" : "=f"(v) : "l"(p));
    return v;
}
__device__ __forceinline__ ull ldg64(const float* p) {
    ull v;
    asm volatile("ld.global.b64 %0, [%1];" : "=l"(v) : "l"(p));
    return v;
}
__device__ __forceinline__ void stcs64(float* p, ull v) {
    asm volatile("st.global.cs.b64 [%0], %1;" :: "l"(p), "l"(v));
}

// ---------------------------------------------------------------------------
// Pass 1: PURE READ stream.  res (128MB) -> n1 -> softmax -> g_attn (3.7MB).
// Blocks 0..511: streaming (1 point/thread, channel-pair f32x2, R3 scheme).
// Blocks 512..525: compute g_nw slice for bn = blk-512 (off critical path).
// ---------------------------------------------------------------------------
__global__ void __launch_bounds__(256, 4) pass1_kernel(
    const float* __restrict__ inp,     // [1,2,7,128]
    const float* __restrict__ res,     // [2, 256, 65536]
    const float* __restrict__ Wres,    // [256, 7]
    const float* __restrict__ nfh,     // [128,1]
    const float* __restrict__ weight)  // [128, 256]
{
    const int tid = threadIdx.x;
    const int bid = blockIdx.x;

    // ---- new_weight GEMM blocks (14 of them; finish early, hidden) ----
    if (bid >= 512) {
        const int bn = bid - 512;        // 0..13 = b*7+n
        float acc = 0.f;
#pragma unroll 16
        for (int h = 0; h < HID; ++h)
            acc += __ldg(inp + bn * HID + h) * weight[h * CH + tid];
        g_nw[bn * CH + tid] = acc;
        return;
    }

    // ---- streaming blocks ----
    __shared__ ull W2[PAIRS][8];         // (w[2k][n], w[2k+1][n])
    __shared__ float sh_n2[8];

    const int b    = bid >> 8;           // 0..1
    const int tile = bid & 255;          // 0..255
    const int wid  = tid >> 5;
    const int lane = tid & 31;

    // n2[b][n] per block: warp w computes node w's 128-dot via shuffle
    if (wid < NODES) {
        float s = 0.f;
#pragma unroll
        for (int i = 0; i < 4; ++i) {
            int h = lane + 32 * i;
            s += __ldg(inp + b * NODES * HID + wid * HID + h) * __ldg(nfh + h);
        }
#pragma unroll
        for (int o = 16; o; o >>= 1)
            s += __shfl_xor_sync(0xffffffffu, s, o);
        if (lane == 0) sh_n2[wid] = s;
    }
    // W2 packing (channel pairs)
    if (tid < PAIRS) {
        const int k = tid;
#pragma unroll
        for (int n = 0; n < NODES; ++n) {
            float w0 = Wres[(2 * k) * NODES + n];
            float w1 = Wres[(2 * k + 1) * NODES + n];
            W2[k][n] = pack2(w0, w1);
        }
        W2[k][7] = 0ull;
    }
    __syncthreads();

    float n2s[NODES];
#pragma unroll
    for (int n = 0; n < NODES; ++n) n2s[n] = sh_n2[n];

    const int p = tile * 256 + tid;
    const float* rfp = res + (size_t)b * CH * P_TOTAL + p;

    ull acc[NODES];
#pragma unroll
    for (int n = 0; n < NODES; ++n) acc[n] = 0ull;

    // n1[p,n] = sum_c rf[c,p]*W[c,n]; f32x2 lanes = even/odd channels
    float a0[PF], a1[PF];
#pragma unroll
    for (int i = 0; i < PF; ++i) {
        a0[i] = ldcs32(rfp + (size_t)(2 * i) * P_TOTAL);
        a1[i] = ldcs32(rfp + (size_t)(2 * i + 1) * P_TOTAL);
    }

#pragma unroll 1
    for (int kb = 0; kb < PAIRS; kb += PF) {
#pragma unroll
        for (int i = 0; i < PF; ++i) {
            ull v = pack2(a0[i], a1[i]);
            if (kb + PF < PAIRS) {
                a0[i] = ldcs32(rfp + (size_t)(2 * (kb + PF + i)) * P_TOTAL);
                a1[i] = ldcs32(rfp + (size_t)(2 * (kb + PF + i) + 1) * P_TOTAL);
            }
            const ulonglong2* wr = (const ulonglong2*)(&W2[kb + i][0]);
            ulonglong2 w01 = wr[0];
            ulonglong2 w23 = wr[1];
            ulonglong2 w45 = wr[2];
            ulonglong2 w6p = wr[3];
            acc[0] = fma2(v, w01.x, acc[0]);
            acc[1] = fma2(v, w01.y, acc[1]);
            acc[2] = fma2(v, w23.x, acc[2]);
            acc[3] = fma2(v, w23.y, acc[3]);
            acc[4] = fma2(v, w45.x, acc[4]);
            acc[5] = fma2(v, w45.y, acc[5]);
            acc[6] = fma2(v, w6p.x, acc[6]);
        }
    }

    // Softmax over 7 nodes; write attn planes (default caching -> L2 resident)
    float s[NODES];
#pragma unroll
    for (int n = 0; n < NODES; ++n) {
        float lo, hi;
        unpack2(acc[n], lo, hi);
        s[n] = lo + hi + n2s[n];
    }
    float m = s[0];
#pragma unroll
    for (int n = 1; n < NODES; ++n) m = fmaxf(m, s[n]);
    float e[NODES], sum = 0.f;
#pragma unroll
    for (int n = 0; n < NODES; ++n) { e[n] = __expf(s[n] - m); sum += e[n]; }
    float inv = __fdividef(1.f, sum);
#pragma unroll
    for (int n = 0; n < NODES; ++n)
        g_attn[(b * NODES + n) * P_TOTAL + p] = e[n] * inv;
}

// ---------------------------------------------------------------------------
// Pass 2: PURE WRITE stream.  g_attn (L2) + g_nw -> out (128MB).
// 2 points/thread (f32x2 lanes = point pair), 256 blocks x 256 threads.
// ---------------------------------------------------------------------------
__global__ void __launch_bounds__(256, 6) pass2_kernel(
    float* __restrict__ out)           // [2, 256, 65536]
{
    __shared__ ull NW[CH][8];          // (nw[n][c], nw[n][c]) duplicated

    const int tid  = threadIdx.x;
    const int b    = blockIdx.x >> 7;   // 0..1 (128 blocks per batch)
    const int tile = blockIdx.x & 127;

    // Stage duplicated new_weight: thread c handles channel c
    {
        const int c = tid;
#pragma unroll
        for (int n = 0; n < NODES; ++n) {
            float q = g_nw[(b * NODES + n) * CH + c];
            NW[c][n] = pack2(q, q);
        }
        NW[c][7] = 0ull;
    }
    __syncthreads();

    const int p0 = tile * 512 + 2 * tid;     // this thread's point pair

    // Load attn for both points: 7 x LDG.64 (L2 hits)
    ull at[NODES];
#pragma unroll
    for (int n = 0; n < NODES; ++n)
        at[n] = ldg64(&g_attn[(b * NODES + n) * P_TOTAL + p0]);

    float* op = out + (size_t)b * CH * P_TOTAL + p0;
#pragma unroll 4
    for (int c = 0; c < CH; ++c) {
        const ulonglong2* nr = (const ulonglong2*)(&NW[c][0]);
        ulonglong2 q01 = nr[0];
        ulonglong2 q23 = nr[1];
        ulonglong2 q45 = nr[2];
        ulonglong2 q6p = nr[3];
        ull o = 0ull;
        o = fma2(at[0], q01.x, o);
        o = fma2(at[1], q01.y, o);
        o = fma2(at[2], q23.x, o);
        o = fma2(at[3], q23.y, o);
        o = fma2(at[4], q45.x, o);
        o = fma2(at[5], q45.y, o);
        o = fma2(at[6], q6p.x, o);
        float v0, v1;
        unpack2(o, v0, v1);
        stcs64(op + (size_t)c * P_TOTAL, pack2(fmaxf(v0, 0.f), fmaxf(v1, 0.f)));
    }
}

// ---------------------------------------------------------------------------
extern "C" void kernel_launch(void* const* d_in, const int* in_sizes, int n_in,
                              void* d_out, int out_size) {
    const float* inp    = (const float*)d_in[0];  // [1,2,7,128]
    const float* res    = (const float*)d_in[1];  // [2,256,16,64,64]
    const float* Wres   = (const float*)d_in[2];  // [256,7]
    const float* nfh    = (const float*)d_in[3];  // [128,1]
    const float* weight = (const float*)d_in[4];  // [128,256]

    pass1_kernel<<<526, 256>>>(inp, res, Wres, nfh, weight);
    pass2_kernel<<<256, 256>>>((float*)d_out);
}